// round 12
// baseline (speedup 1.0000x reference)
#include <cuda_runtime.h>
#include <cuda_bf16.h>
#include <cstdint>
#include <cstddef>

// B=1024, K=50 classes, C=8 centers, H=512
// inputs: d_in[0]=x[1024,512], d_in[1]=class_mu[50,8,512], d_in[2]=mask[8,512], d_in[3]=W[512,512]
// output: concat(mul[1024,8,512] fp32, k_assign[1024,50,8], distances[1024,50,8])
//
// mask is binary {0,1} => per-center K-compaction of the GEMM is EXACT.

// ---------------------------------------------------------------------------
// Scratch (__device__ globals — allocation-free)
// ---------------------------------------------------------------------------
__device__ int   g_kcnt[8];        // kept count per center
__device__ float g_munorm[400];
// compacted, split A: [c][b][1024]: cols [0,512)=hi(x gathered), [512,1024)=lo
__device__ __align__(16) __nv_bfloat16 g_Axc[8 * 1024 * 1024];
// compacted, split, transposed W: [c][n][1024]: hi | lo
__device__ __align__(16) __nv_bfloat16 g_Wc[8 * 512 * 1024];
// bf16 copy of mul, c-major: [c][b][h]
__device__ __align__(16) __nv_bfloat16 g_mulbf16[8 * 1024 * 512];
// bf16 padded class_mu, c-major: [c][k64][h], zeros for k>=50
__device__ __align__(16) __nv_bfloat16 g_mubf16[8 * 64 * 512];
// dot partials: [half][c][b][k64] fp32
__device__ __align__(16) float g_dotp[2][8 * 1024 * 64];
// per-bn partial ||mul[b,c]||^2: [bn][c*1024+b]
__device__ float g_cnormp[4][8 * 1024];

// ---------------------------------------------------------------------------
// PTX helpers (baseline sm_103 target — no 'a'-suffix features)
// ---------------------------------------------------------------------------
__device__ __forceinline__ uint32_t smem_u32(const void* p) {
    uint32_t a;
    asm("{ .reg .u64 t; cvta.to.shared.u64 t, %1; cvt.u32.u64 %0, t; }"
        : "=r"(a) : "l"(p));
    return a;
}

__device__ __forceinline__ void ldsm_x4(uint32_t& r0, uint32_t& r1, uint32_t& r2,
                                        uint32_t& r3, uint32_t addr) {
    asm volatile("ldmatrix.sync.aligned.m8n8.x4.shared.b16 {%0,%1,%2,%3}, [%4];"
                 : "=r"(r0), "=r"(r1), "=r"(r2), "=r"(r3) : "r"(addr));
}

__device__ __forceinline__ void ldsm_x2(uint32_t& r0, uint32_t& r1, uint32_t addr) {
    asm volatile("ldmatrix.sync.aligned.m8n8.x2.shared.b16 {%0,%1}, [%2];"
                 : "=r"(r0), "=r"(r1) : "r"(addr));
}

__device__ __forceinline__ void mma16816(float* c, uint32_t a0, uint32_t a1,
                                         uint32_t a2, uint32_t a3,
                                         uint32_t b0, uint32_t b1) {
    asm volatile(
        "mma.sync.aligned.m16n8k16.row.col.f32.bf16.bf16.f32 "
        "{%0,%1,%2,%3}, {%4,%5,%6,%7}, {%8,%9}, {%0,%1,%2,%3};"
        : "+f"(c[0]), "+f"(c[1]), "+f"(c[2]), "+f"(c[3])
        : "r"(a0), "r"(a1), "r"(a2), "r"(a3), "r"(b0), "r"(b1));
}

#define CP_ASYNC16(dst, src) \
    asm volatile("cp.async.cg.shared.global [%0], [%1], 16;" \
                 :: "r"(dst), "l"(src) : "memory")
#define CP_COMMIT() asm volatile("cp.async.commit_group;" ::: "memory")

// ---------------------------------------------------------------------------
// In-block mask compaction: 256 threads, warp w owns elements [w*64, w*64+64).
// ---------------------------------------------------------------------------
__device__ __forceinline__ int compact_mask(const float* __restrict__ mask_row,
                                            int tid, int* s_kidx, int* s_wcnt) {
    const int lane = tid & 31;
    const int warp = tid >> 5;  // 0..7
    const int e0 = warp * 64 + lane;
    const int e1 = e0 + 32;
    const int p0 = (mask_row[e0] != 0.f) ? 1 : 0;
    const int p1 = (mask_row[e1] != 0.f) ? 1 : 0;
    const unsigned b0 = __ballot_sync(0xffffffffu, p0);
    const unsigned b1 = __ballot_sync(0xffffffffu, p1);
    const int c0 = __popc(b0);
    if (lane == 0) s_wcnt[warp] = c0 + __popc(b1);
    __syncthreads();
    int base = 0, total = 0;
#pragma unroll
    for (int w = 0; w < 8; w++) {
        if (w < warp) base += s_wcnt[w];
        total += s_wcnt[w];
    }
    if (p0) s_kidx[base + __popc(b0 & ((1u << lane) - 1u))] = e0;
    if (p1) s_kidx[base + c0 + __popc(b1 & ((1u << lane) - 1u))] = e1;
    for (int j = total + tid; j < 512; j += 256) s_kidx[j] = 0;
    __syncthreads();
    return total;
}

// ---------------------------------------------------------------------------
// Prep: gather+split A (4 rows/blk) | gather+transpose+split W | munorm | mubf16
// grid = 2048 + 2048 + 50 + 256 = 4402, 256 threads
// ---------------------------------------------------------------------------
__global__ void prep_kernel(const float* __restrict__ x,
                            const float* __restrict__ mask,
                            const float* __restrict__ W,
                            const float* __restrict__ class_mu) {
    __shared__ int s_kidx[512];
    __shared__ int s_wcnt[8];
    __shared__ float s_x[4][512];
    __shared__ float tile[32][33];
    const int tid = threadIdx.x;
    const int blk = blockIdx.x;

    if (blk < 2048) {
        // ---- gather + split A: 4 b-rows per block ----
        const int c = blk >> 8;
        const int bq = blk & 255;
        for (int i = tid; i < 4 * 512; i += 256)
            s_x[i >> 9][i & 511] = x[(size_t)(bq * 4 + (i >> 9)) * 512 + (i & 511)];
        const int total = compact_mask(mask + c * 512, tid, s_kidx, s_wcnt);
        if (bq == 0 && tid == 0) g_kcnt[c] = total;
        const int nch32 = ((total + 31) >> 5) << 5;
        const int j2 = tid * 2;
        if (j2 < nch32) {
            const int i0 = s_kidx[j2];
            const int i1 = s_kidx[j2 + 1];
            const bool v0ok = j2 < total, v1ok = (j2 + 1) < total;
#pragma unroll
            for (int r = 0; r < 4; r++) {
                const float v0 = v0ok ? s_x[r][i0] : 0.f;
                const float v1 = v1ok ? s_x[r][i1] : 0.f;
                const __nv_bfloat16 h0 = __float2bfloat16(v0);
                const __nv_bfloat16 h1 = __float2bfloat16(v1);
                const __nv_bfloat16 l0 = __float2bfloat16(v0 - __bfloat162float(h0));
                const __nv_bfloat16 l1 = __float2bfloat16(v1 - __bfloat162float(h1));
                __nv_bfloat16* base =
                    g_Axc + (((size_t)c * 1024 + bq * 4 + r) << 10);
                *(__nv_bfloat162*)(base + j2)       = __halves2bfloat162(h0, h1);
                *(__nv_bfloat162*)(base + 512 + j2) = __halves2bfloat162(l0, l1);
            }
        }
    } else if (blk < 4096) {
        // ---- gather + transpose + split W ----
        const int t = blk - 2048;
        const int c = t >> 8;
        const int jt = (t >> 4) & 15, nt = t & 15;
        const int total = compact_mask(mask + c * 512, tid, s_kidx, s_wcnt);
        const int nch32 = ((total + 31) >> 5) << 5;
        if (jt * 32 >= nch32) return;
        const int tx = tid & 31, ty = tid >> 5;
#pragma unroll
        for (int i = 0; i < 32; i += 8) {
            const int j = jt * 32 + ty + i;
            tile[ty + i][tx] = (j < total)
                ? W[(size_t)s_kidx[j] * 512 + nt * 32 + tx] : 0.f;
        }
        __syncthreads();
#pragma unroll
        for (int i = 0; i < 32; i += 8) {
            const int n = nt * 32 + ty + i;
            const int j = jt * 32 + tx;
            const float v = tile[tx][ty + i];
            const __nv_bfloat16 hi = __float2bfloat16(v);
            const __nv_bfloat16 lo = __float2bfloat16(v - __bfloat162float(hi));
            __nv_bfloat16* base = g_Wc + (((size_t)c * 512 + n) << 10);
            base[j] = hi;
            base[512 + j] = lo;
        }
    } else if (blk < 4096 + 50) {
        // ---- munorm ----
        const int warp = tid >> 5;
        const int lane = tid & 31;
        const int r = (blk - 4096) * 8 + warp;
        const float4* row = (const float4*)(class_mu + (size_t)r * 512);
        float s = 0.f;
#pragma unroll
        for (int j = lane; j < 128; j += 32) {
            float4 v = row[j];
            s += v.x * v.x + v.y * v.y + v.z * v.z + v.w * v.w;
        }
#pragma unroll
        for (int o = 16; o; o >>= 1) s += __shfl_down_sync(0xffffffffu, s, o);
        if (lane == 0) g_munorm[r] = s;
    } else {
        // ---- class_mu -> g_mubf16[c][k64][h], zero padded ----
        const int t = blk - 4146;
        const int idx4 = t * 256 + tid;
        const int row = idx4 >> 7;
        const int h = (idx4 & 127) << 2;
        const int c = row >> 6, k = row & 63;
        float4 v = make_float4(0.f, 0.f, 0.f, 0.f);
        if (k < 50) v = *(const float4*)(class_mu + (((size_t)k * 8 + c) << 9) + h);
        __nv_bfloat162* dst = (__nv_bfloat162*)(g_mubf16 + (size_t)row * 512 + h);
        dst[0] = __halves2bfloat162(__float2bfloat16(v.x), __float2bfloat16(v.y));
        dst[1] = __halves2bfloat162(__float2bfloat16(v.z), __float2bfloat16(v.w));
    }
}

// ---------------------------------------------------------------------------
// K-compacted HMMA GEMM, per-center: mul[b,c,:] = Axc[c] @ Wc[c]^T
// <<<dim3(4, 64), 256, 81920>>>, blockIdx.y = c*8 + bm
// ---------------------------------------------------------------------------
#define SM_STRIDE 80
#define BUF_BYTES 20480

__global__ void __launch_bounds__(256, 2)
mma_gemm_kernel(float* __restrict__ out) {
    extern __shared__ __align__(16) char smem[];  // 4 * BUF_BYTES
    __shared__ float s_part[4][128];
    const uint32_t smem_base = smem_u32(smem);

    const int tid = threadIdx.x;
    const int lane = tid & 31;
    const int wid = tid >> 5;
    const int wm = wid >> 2;
    const int wn = wid & 3;
    const int bn = blockIdx.x;
    const int c  = blockIdx.y >> 3;
    const int bm = blockIdx.y & 7;

    const int kcnt = g_kcnt[c];
    const int nch = (kcnt + 31) >> 5;
    const int T = 3 * nch;

    const __nv_bfloat16* Abase = g_Axc + (((size_t)c * 1024 + bm * 128) << 10);
    const __nv_bfloat16* Bbase = g_Wc  + (((size_t)c * 512  + bn * 128) << 10);

    const int lrow = tid >> 2;
    const int lseg = tid & 3;

    auto issue = [&](int t) {
        const int stage = t & 3;
        const int p = (t >= 2 * nch) ? 2 : ((t >= nch) ? 1 : 0);
        const int sub = t - p * nch;
        const int acol = ((p == 2) ? 512 : 0) + sub * 32;  // A: hi,hi,lo
        const int bcol = ((p == 1) ? 512 : 0) + sub * 32;  // B: hi,lo,hi
        const uint32_t sA = smem_base + stage * BUF_BYTES;
        const uint32_t sB = sA + 128 * SM_STRIDE;
#pragma unroll
        for (int q = 0; q < 2; q++) {
            const int row = lrow + q * 64;
            CP_ASYNC16(sA + row * SM_STRIDE + lseg * 16,
                       Abase + ((size_t)row << 10) + acol + lseg * 8);
        }
#pragma unroll
        for (int q = 0; q < 2; q++) {
            const int row = lrow + q * 64;
            CP_ASYNC16(sB + row * SM_STRIDE + lseg * 16,
                       Bbase + ((size_t)row << 10) + bcol + lseg * 8);
        }
        CP_COMMIT();
    };

    float acc[4][4][4];
#pragma unroll
    for (int i = 0; i < 4; i++)
#pragma unroll
        for (int j = 0; j < 4; j++)
#pragma unroll
            for (int q = 0; q < 4; q++) acc[i][j][q] = 0.f;

    issue(0);
    issue(1);
    issue(2);

    for (int t = 0; t < T; t++) {
        if (t <= T - 3)      asm volatile("cp.async.wait_group 2;" ::: "memory");
        else if (t == T - 2) asm volatile("cp.async.wait_group 1;" ::: "memory");
        else                 asm volatile("cp.async.wait_group 0;" ::: "memory");
        __syncthreads();
        if (t + 3 < T) issue(t + 3);

        const uint32_t sA = smem_base + (t & 3) * BUF_BYTES;
        const uint32_t sB = sA + 128 * SM_STRIDE;
#pragma unroll
        for (int ks = 0; ks < 2; ks++) {
            uint32_t a[4][4];
#pragma unroll
            for (int mf = 0; mf < 4; mf++) {
                const int row = wm * 64 + mf * 16 + (lane & 15);
                const uint32_t col = ks * 32 + ((lane >> 4) << 4);
                ldsm_x4(a[mf][0], a[mf][1], a[mf][2], a[mf][3],
                        sA + row * SM_STRIDE + col);
            }
            uint32_t b[4][2];
#pragma unroll
            for (int nf = 0; nf < 4; nf++) {
                const int row = wn * 32 + nf * 8 + (lane & 7);
                const uint32_t col = ks * 32 + (((lane >> 3) & 1) << 4);
                ldsm_x2(b[nf][0], b[nf][1], sB + row * SM_STRIDE + col);
            }
#pragma unroll
            for (int mf = 0; mf < 4; mf++)
#pragma unroll
                for (int nf = 0; nf < 4; nf++)
                    mma16816(acc[mf][nf], a[mf][0], a[mf][1], a[mf][2], a[mf][3],
                             b[nf][0], b[nf][1]);
        }
    }

    // ---- Epilogue 1: stores (fp32 out, bf16 c-major copy) ----
    const int r0 = lane >> 2;
    const int c0 = (lane & 3) << 1;
#pragma unroll
    for (int mf = 0; mf < 4; mf++) {
        const int bl = bm * 128 + wm * 64 + mf * 16 + r0;
#pragma unroll
        for (int nf = 0; nf < 4; nf++) {
            const int n = bn * 128 + wn * 32 + nf * 8 + c0;
            *(float2*)(out + (((size_t)bl * 8 + c) << 9) + n) =
                make_float2(acc[mf][nf][0], acc[mf][nf][1]);
            *(float2*)(out + (((size_t)(bl + 8) * 8 + c) << 9) + n) =
                make_float2(acc[mf][nf][2], acc[mf][nf][3]);
            *(__nv_bfloat162*)(g_mulbf16 + (((size_t)c * 1024 + bl) << 9) + n) =
                __halves2bfloat162(__float2bfloat16(acc[mf][nf][0]),
                                   __float2bfloat16(acc[mf][nf][1]));
            *(__nv_bfloat162*)(g_mulbf16 + (((size_t)c * 1024 + bl + 8) << 9) + n) =
                __halves2bfloat162(__float2bfloat16(acc[mf][nf][2]),
                                   __float2bfloat16(acc[mf][nf][3]));
        }
    }

    // ---- Epilogue 2: partial cnorm over this CTA's 128 n-cols ----
#pragma unroll
    for (int mf = 0; mf < 4; mf++) {
        float p1 = 0.f, p2 = 0.f;
#pragma unroll
        for (int nf = 0; nf < 4; nf++) {
            p1 += acc[mf][nf][0] * acc[mf][nf][0] + acc[mf][nf][1] * acc[mf][nf][1];
            p2 += acc[mf][nf][2] * acc[mf][nf][2] + acc[mf][nf][3] * acc[mf][nf][3];
        }
        p1 += __shfl_xor_sync(0xffffffffu, p1, 1);
        p1 += __shfl_xor_sync(0xffffffffu, p1, 2);
        p2 += __shfl_xor_sync(0xffffffffu, p2, 1);
        p2 += __shfl_xor_sync(0xffffffffu, p2, 2);
        if ((lane & 3) == 0) {
            s_part[wn][wm * 64 + mf * 16 + r0] = p1;
            s_part[wn][wm * 64 + mf * 16 + r0 + 8] = p2;
        }
    }
    __syncthreads();
    if (tid < 128) {
        const float cn = s_part[0][tid] + s_part[1][tid]
                       + s_part[2][tid] + s_part[3][tid];
        g_cnormp[bn][c * 1024 + bm * 128 + tid] = cn;
    }
}

// ---------------------------------------------------------------------------
// Dot HMMA (h-split by 2): g_dotp[hh][c][b][k64] partial over 256 h-cols.
// <<<256, 256, 73728>>>, blockIdx.x = hh*128 + bt*8 + c
// ---------------------------------------------------------------------------
#define DSTRIDE 144
#define DBUF (128 * DSTRIDE)

__global__ void __launch_bounds__(256)
dot_mma_kernel() {
    extern __shared__ __align__(16) char smem[];  // 4 * DBUF
    const uint32_t smem_base = smem_u32(smem);

    const int tid = threadIdx.x;
    const int lane = tid & 31;
    const int wid = tid >> 5;
    const int wm = wid >> 1;
    const int wn = wid & 1;
    const int c = blockIdx.x & 7;
    const int bt = (blockIdx.x >> 3) & 15;
    const int hh = blockIdx.x >> 7;

    const __nv_bfloat16* Abase =
        g_mulbf16 + (((size_t)c * 1024 + bt * 64) << 9) + hh * 256;
    const __nv_bfloat16* Bbase = g_mubf16 + ((size_t)c << 15) + hh * 256;

    const int lrow = tid >> 3;
    const int lseg = tid & 7;

    auto issue = [&](int ch) {
        const int stage = ch & 3;
        const uint32_t sA = smem_base + stage * DBUF;
        const uint32_t sB = sA + 64 * DSTRIDE;
#pragma unroll
        for (int q = 0; q < 2; q++) {
            const int row = lrow + q * 32;
            CP_ASYNC16(sA + row * DSTRIDE + lseg * 16,
                       Abase + ((size_t)row << 9) + ch * 64 + lseg * 8);
        }
#pragma unroll
        for (int q = 0; q < 2; q++) {
            const int row = lrow + q * 32;
            CP_ASYNC16(sB + row * DSTRIDE + lseg * 16,
                       Bbase + ((size_t)row << 9) + ch * 64 + lseg * 8);
        }
        CP_COMMIT();
    };

    float acc[4][4];
#pragma unroll
    for (int j = 0; j < 4; j++)
#pragma unroll
        for (int q = 0; q < 4; q++) acc[j][q] = 0.f;

    issue(0);
    issue(1);
    issue(2);

    for (int ch = 0; ch < 4; ch++) {
        if (ch <= 1)      asm volatile("cp.async.wait_group 2;" ::: "memory");
        else if (ch == 2) asm volatile("cp.async.wait_group 1;" ::: "memory");
        else              asm volatile("cp.async.wait_group 0;" ::: "memory");
        __syncthreads();
        if (ch + 3 < 4) issue(ch + 3);

        const uint32_t sA = smem_base + (ch & 3) * DBUF;
        const uint32_t sB = sA + 64 * DSTRIDE;
#pragma unroll
        for (int ks = 0; ks < 4; ks++) {
            uint32_t a[4];
            {
                const int row = wm * 16 + (lane & 15);
                const uint32_t col = ks * 32 + ((lane >> 4) << 4);
                ldsm_x4(a[0], a[1], a[2], a[3], sA + row * DSTRIDE + col);
            }
            uint32_t b[4][2];
#pragma unroll
            for (int nf = 0; nf < 4; nf++) {
                const int row = wn * 32 + nf * 8 + (lane & 7);
                const uint32_t col = ks * 32 + (((lane >> 3) & 1) << 4);
                ldsm_x2(b[nf][0], b[nf][1], sB + row * DSTRIDE + col);
            }
#pragma unroll
            for (int nf = 0; nf < 4; nf++)
                mma16816(acc[nf], a[0], a[1], a[2], a[3], b[nf][0], b[nf][1]);
        }
    }

    const int r0 = lane >> 2;
    const int c0 = (lane & 3) << 1;
    const int m = bt * 64 + wm * 16 + r0;
    float* dbase = g_dotp[hh] + (((size_t)c * 1024 + m) << 6);
#pragma unroll
    for (int nf = 0; nf < 4; nf++) {
        const int n = wn * 32 + nf * 8 + c0;
        *(float2*)(dbase + n) = make_float2(acc[nf][0], acc[nf][1]);
        *(float2*)(dbase + (8 << 6) + n) = make_float2(acc[nf][2], acc[nf][3]);
    }
}

// ---------------------------------------------------------------------------
// Epilogue: coalesced smem staging of dots, then distances/k_assign.
// One block = 8 b-rows. <<<128, 256>>>
// ---------------------------------------------------------------------------
__global__ void __launch_bounds__(256)
score_epilogue_kernel(float* __restrict__ out_ka, float* __restrict__ out_dist) {
    __shared__ float s_dot[8][8][64];   // [c][bsub][k]  16 KB
    __shared__ float s_cnorm[64];       // [bsub*8+c]
    const int tid = threadIdx.x;
    const int b0 = blockIdx.x;          // b rows b0*8 .. b0*8+7

    // Bulk-load dots: 64 rows (c,bsub) x 64 floats, both halves summed.
    // 1024 float4 positions, 4 per thread, fully coalesced per row.
#pragma unroll
    for (int it = 0; it < 4; it++) {
        const int pos = tid + it * 256;          // 0..1023
        const int r = pos >> 4;                  // 0..63 = c*8+bsub
        const int seg = pos & 15;                // float4 index within row
        const int c = r >> 3, bsub = r & 7;
        const size_t gi = ((((size_t)c * 1024 + b0 * 8 + bsub) << 6) + seg * 4);
        const float4 u = *(const float4*)(g_dotp[0] + gi);
        const float4 v = *(const float4*)(g_dotp[1] + gi);
        *(float4*)&s_dot[c][bsub][seg * 4] =
            make_float4(u.x + v.x, u.y + v.y, u.z + v.z, u.w + v.w);
    }
    if (tid < 64) {
        const int bsub = tid >> 3, cc = tid & 7;
        const int b = b0 * 8 + bsub;
        s_cnorm[tid] = g_cnormp[0][cc * 1024 + b] + g_cnormp[1][cc * 1024 + b]
                     + g_cnormp[2][cc * 1024 + b] + g_cnormp[3][cc * 1024 + b];
    }
    __syncthreads();

    for (int p = tid; p < 400; p += 256) {
        const int bsub = p / 50;
        const int k = p % 50;
        const int b = b0 * 8 + bsub;
        float sc[8];
        float S = 0.f;
#pragma unroll
        for (int c = 0; c < 8; c++) {
            const float d2 = 1.f + s_cnorm[bsub * 8 + c] - 2.f * s_dot[c][bsub][k]
                           + g_munorm[k * 8 + c];
            const float v = 1.f / d2;
            sc[c] = v;
            S += v;
        }
        const float inv1 = 1.f / (S + 1e-8f);
        float dist[8];
        float T = 0.f;
#pragma unroll
        for (int c = 0; c < 8; c++) { dist[c] = sc[c] * inv1; T += dist[c]; }
        const float inv2 = 1.f / T;
        const size_t base = ((size_t)b * 50 + k) << 3;
        float4 d01 = make_float4(dist[0], dist[1], dist[2], dist[3]);
        float4 d23 = make_float4(dist[4], dist[5], dist[6], dist[7]);
        *(float4*)(out_dist + base) = d01;
        *(float4*)(out_dist + base + 4) = d23;
        *(float4*)(out_ka + base) =
            make_float4(d01.x * inv2, d01.y * inv2, d01.z * inv2, d01.w * inv2);
        *(float4*)(out_ka + base + 4) =
            make_float4(d23.x * inv2, d23.y * inv2, d23.z * inv2, d23.w * inv2);
    }
}

// ---------------------------------------------------------------------------
extern "C" void kernel_launch(void* const* d_in, const int* in_sizes, int n_in,
                              void* d_out, int out_size) {
    const float* x        = (const float*)d_in[0];
    const float* class_mu = (const float*)d_in[1];
    const float* mask     = (const float*)d_in[2];
    const float* W        = (const float*)d_in[3];

    float* out      = (float*)d_out;
    float* out_mul  = out;                                  // 1024*8*512
    float* out_ka   = out + (size_t)1024 * 8 * 512;         // 1024*50*8
    float* out_dist = out_ka + (size_t)1024 * 50 * 8;       // 1024*50*8

    const size_t gemm_smem = 4 * BUF_BYTES;  // 81920 B
    const size_t dot_smem  = 4 * DBUF;       // 73728 B
    cudaFuncSetAttribute(mma_gemm_kernel,
                         cudaFuncAttributeMaxDynamicSharedMemorySize, (int)gemm_smem);
    cudaFuncSetAttribute(dot_mma_kernel,
                         cudaFuncAttributeMaxDynamicSharedMemorySize, (int)dot_smem);

    prep_kernel<<<4402, 256>>>(x, mask, W, class_mu);
    mma_gemm_kernel<<<dim3(4, 64), 256, gemm_smem>>>(out_mul);
    dot_mma_kernel<<<256, 256, dot_smem>>>();
    score_epilogue_kernel<<<128, 256>>>(out_ka, out_dist);
}

// round 13
// speedup vs baseline: 1.0120x; 1.0120x over previous
#include <cuda_runtime.h>
#include <cuda_bf16.h>
#include <cstdint>
#include <cstddef>

// B=1024, K=50 classes, C=8 centers, H=512
// inputs: d_in[0]=x[1024,512], d_in[1]=class_mu[50,8,512], d_in[2]=mask[8,512], d_in[3]=W[512,512]
// output: concat(mul[1024,8,512] fp32, k_assign[1024,50,8], distances[1024,50,8])
//
// mask is binary {0,1} => per-center K-compaction of the GEMM is EXACT.

// ---------------------------------------------------------------------------
// Scratch (__device__ globals — allocation-free)
// ---------------------------------------------------------------------------
__device__ int   g_kcnt[8];        // kept count per center
__device__ float g_munorm[400];
// compacted, split A: [c][b][1024]: cols [0,512)=hi(x gathered), [512,1024)=lo
__device__ __align__(16) __nv_bfloat16 g_Axc[8 * 1024 * 1024];
// compacted, split, transposed W: [c][n][1024]: hi | lo
__device__ __align__(16) __nv_bfloat16 g_Wc[8 * 512 * 1024];
// bf16 copy of mul, c-major: [c][b][h]
__device__ __align__(16) __nv_bfloat16 g_mulbf16[8 * 1024 * 512];
// bf16 padded class_mu, c-major: [c][k64][h], zeros for k>=50
__device__ __align__(16) __nv_bfloat16 g_mubf16[8 * 64 * 512];
// dot partials: [half][c][b][k64] fp32
__device__ __align__(16) float g_dotp[2][8 * 1024 * 64];
// per-bn partial ||mul[b,c]||^2: [bn][c*1024+b]
__device__ float g_cnormp[4][8 * 1024];

// ---------------------------------------------------------------------------
// PTX helpers (baseline sm_103 target — no 'a'-suffix features)
// ---------------------------------------------------------------------------
__device__ __forceinline__ uint32_t smem_u32(const void* p) {
    uint32_t a;
    asm("{ .reg .u64 t; cvta.to.shared.u64 t, %1; cvt.u32.u64 %0, t; }"
        : "=r"(a) : "l"(p));
    return a;
}

__device__ __forceinline__ void ldsm_x4(uint32_t& r0, uint32_t& r1, uint32_t& r2,
                                        uint32_t& r3, uint32_t addr) {
    asm volatile("ldmatrix.sync.aligned.m8n8.x4.shared.b16 {%0,%1,%2,%3}, [%4];"
                 : "=r"(r0), "=r"(r1), "=r"(r2), "=r"(r3) : "r"(addr));
}

__device__ __forceinline__ void ldsm_x2(uint32_t& r0, uint32_t& r1, uint32_t addr) {
    asm volatile("ldmatrix.sync.aligned.m8n8.x2.shared.b16 {%0,%1}, [%2];"
                 : "=r"(r0), "=r"(r1) : "r"(addr));
}

__device__ __forceinline__ void mma16816(float* c, uint32_t a0, uint32_t a1,
                                         uint32_t a2, uint32_t a3,
                                         uint32_t b0, uint32_t b1) {
    asm volatile(
        "mma.sync.aligned.m16n8k16.row.col.f32.bf16.bf16.f32 "
        "{%0,%1,%2,%3}, {%4,%5,%6,%7}, {%8,%9}, {%0,%1,%2,%3};"
        : "+f"(c[0]), "+f"(c[1]), "+f"(c[2]), "+f"(c[3])
        : "r"(a0), "r"(a1), "r"(a2), "r"(a3), "r"(b0), "r"(b1));
}

#define CP_ASYNC16(dst, src) \
    asm volatile("cp.async.cg.shared.global [%0], [%1], 16;" \
                 :: "r"(dst), "l"(src) : "memory")
#define CP_COMMIT() asm volatile("cp.async.commit_group;" ::: "memory")

// ---------------------------------------------------------------------------
// In-block mask compaction: 256 threads, warp w owns elements [w*64, w*64+64).
// ---------------------------------------------------------------------------
__device__ __forceinline__ int compact_mask(const float* __restrict__ mask_row,
                                            int tid, int* s_kidx, int* s_wcnt) {
    const int lane = tid & 31;
    const int warp = tid >> 5;  // 0..7
    const int e0 = warp * 64 + lane;
    const int e1 = e0 + 32;
    const int p0 = (mask_row[e0] != 0.f) ? 1 : 0;
    const int p1 = (mask_row[e1] != 0.f) ? 1 : 0;
    const unsigned b0 = __ballot_sync(0xffffffffu, p0);
    const unsigned b1 = __ballot_sync(0xffffffffu, p1);
    const int c0 = __popc(b0);
    if (lane == 0) s_wcnt[warp] = c0 + __popc(b1);
    __syncthreads();
    int base = 0, total = 0;
#pragma unroll
    for (int w = 0; w < 8; w++) {
        if (w < warp) base += s_wcnt[w];
        total += s_wcnt[w];
    }
    if (p0) s_kidx[base + __popc(b0 & ((1u << lane) - 1u))] = e0;
    if (p1) s_kidx[base + c0 + __popc(b1 & ((1u << lane) - 1u))] = e1;
    for (int j = total + tid; j < 512; j += 256) s_kidx[j] = 0;
    __syncthreads();
    return total;
}

// ---------------------------------------------------------------------------
// Prep: gather+split A (4 rows/blk) | gather+transpose+split W | munorm | mubf16
// grid = 2048 + 2048 + 50 + 256 = 4402, 256 threads
// ---------------------------------------------------------------------------
__global__ void prep_kernel(const float* __restrict__ x,
                            const float* __restrict__ mask,
                            const float* __restrict__ W,
                            const float* __restrict__ class_mu) {
    __shared__ int s_kidx[512];
    __shared__ int s_wcnt[8];
    __shared__ float s_x[4][512];
    __shared__ float tile[32][33];
    const int tid = threadIdx.x;
    const int blk = blockIdx.x;

    if (blk < 2048) {
        // ---- gather + split A: 4 b-rows per block ----
        const int c = blk >> 8;
        const int bq = blk & 255;
        for (int i = tid; i < 4 * 512; i += 256)
            s_x[i >> 9][i & 511] = x[(size_t)(bq * 4 + (i >> 9)) * 512 + (i & 511)];
        const int total = compact_mask(mask + c * 512, tid, s_kidx, s_wcnt);
        if (bq == 0 && tid == 0) g_kcnt[c] = total;
        const int nch32 = ((total + 31) >> 5) << 5;
        const int j2 = tid * 2;
        if (j2 < nch32) {
            const int i0 = s_kidx[j2];
            const int i1 = s_kidx[j2 + 1];
            const bool v0ok = j2 < total, v1ok = (j2 + 1) < total;
#pragma unroll
            for (int r = 0; r < 4; r++) {
                const float v0 = v0ok ? s_x[r][i0] : 0.f;
                const float v1 = v1ok ? s_x[r][i1] : 0.f;
                const __nv_bfloat16 h0 = __float2bfloat16(v0);
                const __nv_bfloat16 h1 = __float2bfloat16(v1);
                const __nv_bfloat16 l0 = __float2bfloat16(v0 - __bfloat162float(h0));
                const __nv_bfloat16 l1 = __float2bfloat16(v1 - __bfloat162float(h1));
                __nv_bfloat16* base =
                    g_Axc + (((size_t)c * 1024 + bq * 4 + r) << 10);
                *(__nv_bfloat162*)(base + j2)       = __halves2bfloat162(h0, h1);
                *(__nv_bfloat162*)(base + 512 + j2) = __halves2bfloat162(l0, l1);
            }
        }
    } else if (blk < 4096) {
        // ---- gather + transpose + split W ----
        const int t = blk - 2048;
        const int c = t >> 8;
        const int jt = (t >> 4) & 15, nt = t & 15;
        const int total = compact_mask(mask + c * 512, tid, s_kidx, s_wcnt);
        const int nch32 = ((total + 31) >> 5) << 5;
        if (jt * 32 >= nch32) return;
        const int tx = tid & 31, ty = tid >> 5;
#pragma unroll
        for (int i = 0; i < 32; i += 8) {
            const int j = jt * 32 + ty + i;
            tile[ty + i][tx] = (j < total)
                ? W[(size_t)s_kidx[j] * 512 + nt * 32 + tx] : 0.f;
        }
        __syncthreads();
#pragma unroll
        for (int i = 0; i < 32; i += 8) {
            const int n = nt * 32 + ty + i;
            const int j = jt * 32 + tx;
            const float v = tile[tx][ty + i];
            const __nv_bfloat16 hi = __float2bfloat16(v);
            const __nv_bfloat16 lo = __float2bfloat16(v - __bfloat162float(hi));
            __nv_bfloat16* base = g_Wc + (((size_t)c * 512 + n) << 10);
            base[j] = hi;
            base[512 + j] = lo;
        }
    } else if (blk < 4096 + 50) {
        // ---- munorm ----
        const int warp = tid >> 5;
        const int lane = tid & 31;
        const int r = (blk - 4096) * 8 + warp;
        const float4* row = (const float4*)(class_mu + (size_t)r * 512);
        float s = 0.f;
#pragma unroll
        for (int j = lane; j < 128; j += 32) {
            float4 v = row[j];
            s += v.x * v.x + v.y * v.y + v.z * v.z + v.w * v.w;
        }
#pragma unroll
        for (int o = 16; o; o >>= 1) s += __shfl_down_sync(0xffffffffu, s, o);
        if (lane == 0) g_munorm[r] = s;
    } else {
        // ---- class_mu -> g_mubf16[c][k64][h], zero padded ----
        const int t = blk - 4146;
        const int idx4 = t * 256 + tid;
        const int row = idx4 >> 7;
        const int h = (idx4 & 127) << 2;
        const int c = row >> 6, k = row & 63;
        float4 v = make_float4(0.f, 0.f, 0.f, 0.f);
        if (k < 50) v = *(const float4*)(class_mu + (((size_t)k * 8 + c) << 9) + h);
        __nv_bfloat162* dst = (__nv_bfloat162*)(g_mubf16 + (size_t)row * 512 + h);
        dst[0] = __halves2bfloat162(__float2bfloat16(v.x), __float2bfloat16(v.y));
        dst[1] = __halves2bfloat162(__float2bfloat16(v.z), __float2bfloat16(v.w));
    }
}

// ---------------------------------------------------------------------------
// K-compacted HMMA GEMM, per-center: mul[b,c,:] = Axc[c] @ Wc[c]^T
// <<<dim3(4, 64), 256, 81920>>>, blockIdx.y = c*8 + bm
// ---------------------------------------------------------------------------
#define SM_STRIDE 80
#define BUF_BYTES 20480

__global__ void __launch_bounds__(256, 2)
mma_gemm_kernel(float* __restrict__ out) {
    extern __shared__ __align__(16) char smem[];  // 4 * BUF_BYTES
    __shared__ float s_part[4][128];
    const uint32_t smem_base = smem_u32(smem);

    const int tid = threadIdx.x;
    const int lane = tid & 31;
    const int wid = tid >> 5;
    const int wm = wid >> 2;
    const int wn = wid & 3;
    const int bn = blockIdx.x;
    const int c  = blockIdx.y >> 3;
    const int bm = blockIdx.y & 7;

    const int kcnt = g_kcnt[c];
    const int nch = (kcnt + 31) >> 5;
    const int T = 3 * nch;

    const __nv_bfloat16* Abase = g_Axc + (((size_t)c * 1024 + bm * 128) << 10);
    const __nv_bfloat16* Bbase = g_Wc  + (((size_t)c * 512  + bn * 128) << 10);

    const int lrow = tid >> 2;
    const int lseg = tid & 3;

    auto issue = [&](int t) {
        const int stage = t & 3;
        const int p = (t >= 2 * nch) ? 2 : ((t >= nch) ? 1 : 0);
        const int sub = t - p * nch;
        const int acol = ((p == 2) ? 512 : 0) + sub * 32;  // A: hi,hi,lo
        const int bcol = ((p == 1) ? 512 : 0) + sub * 32;  // B: hi,lo,hi
        const uint32_t sA = smem_base + stage * BUF_BYTES;
        const uint32_t sB = sA + 128 * SM_STRIDE;
#pragma unroll
        for (int q = 0; q < 2; q++) {
            const int row = lrow + q * 64;
            CP_ASYNC16(sA + row * SM_STRIDE + lseg * 16,
                       Abase + ((size_t)row << 10) + acol + lseg * 8);
        }
#pragma unroll
        for (int q = 0; q < 2; q++) {
            const int row = lrow + q * 64;
            CP_ASYNC16(sB + row * SM_STRIDE + lseg * 16,
                       Bbase + ((size_t)row << 10) + bcol + lseg * 8);
        }
        CP_COMMIT();
    };

    float acc[4][4][4];
#pragma unroll
    for (int i = 0; i < 4; i++)
#pragma unroll
        for (int j = 0; j < 4; j++)
#pragma unroll
            for (int q = 0; q < 4; q++) acc[i][j][q] = 0.f;

    issue(0);
    issue(1);
    issue(2);

    for (int t = 0; t < T; t++) {
        if (t <= T - 3)      asm volatile("cp.async.wait_group 2;" ::: "memory");
        else if (t == T - 2) asm volatile("cp.async.wait_group 1;" ::: "memory");
        else                 asm volatile("cp.async.wait_group 0;" ::: "memory");
        __syncthreads();
        if (t + 3 < T) issue(t + 3);

        const uint32_t sA = smem_base + (t & 3) * BUF_BYTES;
        const uint32_t sB = sA + 128 * SM_STRIDE;
#pragma unroll
        for (int ks = 0; ks < 2; ks++) {
            uint32_t a[4][4];
#pragma unroll
            for (int mf = 0; mf < 4; mf++) {
                const int row = wm * 64 + mf * 16 + (lane & 15);
                const uint32_t col = ks * 32 + ((lane >> 4) << 4);
                ldsm_x4(a[mf][0], a[mf][1], a[mf][2], a[mf][3],
                        sA + row * SM_STRIDE + col);
            }
            uint32_t b[4][2];
#pragma unroll
            for (int nf = 0; nf < 4; nf++) {
                const int row = wn * 32 + nf * 8 + (lane & 7);
                const uint32_t col = ks * 32 + (((lane >> 3) & 1) << 4);
                ldsm_x2(b[nf][0], b[nf][1], sB + row * SM_STRIDE + col);
            }
#pragma unroll
            for (int mf = 0; mf < 4; mf++)
#pragma unroll
                for (int nf = 0; nf < 4; nf++)
                    mma16816(acc[mf][nf], a[mf][0], a[mf][1], a[mf][2], a[mf][3],
                             b[nf][0], b[nf][1]);
        }
    }

    // ---- Epilogue 1: stores (fp32 out, bf16 c-major copy) ----
    const int r0 = lane >> 2;
    const int c0 = (lane & 3) << 1;
#pragma unroll
    for (int mf = 0; mf < 4; mf++) {
        const int bl = bm * 128 + wm * 64 + mf * 16 + r0;
#pragma unroll
        for (int nf = 0; nf < 4; nf++) {
            const int n = bn * 128 + wn * 32 + nf * 8 + c0;
            *(float2*)(out + (((size_t)bl * 8 + c) << 9) + n) =
                make_float2(acc[mf][nf][0], acc[mf][nf][1]);
            *(float2*)(out + (((size_t)(bl + 8) * 8 + c) << 9) + n) =
                make_float2(acc[mf][nf][2], acc[mf][nf][3]);
            *(__nv_bfloat162*)(g_mulbf16 + (((size_t)c * 1024 + bl) << 9) + n) =
                __halves2bfloat162(__float2bfloat16(acc[mf][nf][0]),
                                   __float2bfloat16(acc[mf][nf][1]));
            *(__nv_bfloat162*)(g_mulbf16 + (((size_t)c * 1024 + bl + 8) << 9) + n) =
                __halves2bfloat162(__float2bfloat16(acc[mf][nf][2]),
                                   __float2bfloat16(acc[mf][nf][3]));
        }
    }

    // ---- Epilogue 2: partial cnorm over this CTA's 128 n-cols ----
#pragma unroll
    for (int mf = 0; mf < 4; mf++) {
        float p1 = 0.f, p2 = 0.f;
#pragma unroll
        for (int nf = 0; nf < 4; nf++) {
            p1 += acc[mf][nf][0] * acc[mf][nf][0] + acc[mf][nf][1] * acc[mf][nf][1];
            p2 += acc[mf][nf][2] * acc[mf][nf][2] + acc[mf][nf][3] * acc[mf][nf][3];
        }
        p1 += __shfl_xor_sync(0xffffffffu, p1, 1);
        p1 += __shfl_xor_sync(0xffffffffu, p1, 2);
        p2 += __shfl_xor_sync(0xffffffffu, p2, 1);
        p2 += __shfl_xor_sync(0xffffffffu, p2, 2);
        if ((lane & 3) == 0) {
            s_part[wn][wm * 64 + mf * 16 + r0] = p1;
            s_part[wn][wm * 64 + mf * 16 + r0 + 8] = p2;
        }
    }
    __syncthreads();
    if (tid < 128) {
        const float cn = s_part[0][tid] + s_part[1][tid]
                       + s_part[2][tid] + s_part[3][tid];
        g_cnormp[bn][c * 1024 + bm * 128 + tid] = cn;
    }
}

// ---------------------------------------------------------------------------
// Dot HMMA (h-split by 2): g_dotp[hh][c][b][k64] partial over 256 h-cols.
// <<<256, 256, 73728>>>, blockIdx.x = hh*128 + bt*8 + c
// ---------------------------------------------------------------------------
#define DSTRIDE 144
#define DBUF (128 * DSTRIDE)

__global__ void __launch_bounds__(256)
dot_mma_kernel() {
    extern __shared__ __align__(16) char smem[];  // 4 * DBUF
    const uint32_t smem_base = smem_u32(smem);

    const int tid = threadIdx.x;
    const int lane = tid & 31;
    const int wid = tid >> 5;
    const int wm = wid >> 1;
    const int wn = wid & 1;
    const int c = blockIdx.x & 7;
    const int bt = (blockIdx.x >> 3) & 15;
    const int hh = blockIdx.x >> 7;

    const __nv_bfloat16* Abase =
        g_mulbf16 + (((size_t)c * 1024 + bt * 64) << 9) + hh * 256;
    const __nv_bfloat16* Bbase = g_mubf16 + ((size_t)c << 15) + hh * 256;

    const int lrow = tid >> 3;
    const int lseg = tid & 7;

    auto issue = [&](int ch) {
        const int stage = ch & 3;
        const uint32_t sA = smem_base + stage * DBUF;
        const uint32_t sB = sA + 64 * DSTRIDE;
#pragma unroll
        for (int q = 0; q < 2; q++) {
            const int row = lrow + q * 32;
            CP_ASYNC16(sA + row * DSTRIDE + lseg * 16,
                       Abase + ((size_t)row << 9) + ch * 64 + lseg * 8);
        }
#pragma unroll
        for (int q = 0; q < 2; q++) {
            const int row = lrow + q * 32;
            CP_ASYNC16(sB + row * DSTRIDE + lseg * 16,
                       Bbase + ((size_t)row << 9) + ch * 64 + lseg * 8);
        }
        CP_COMMIT();
    };

    float acc[4][4];
#pragma unroll
    for (int j = 0; j < 4; j++)
#pragma unroll
        for (int q = 0; q < 4; q++) acc[j][q] = 0.f;

    issue(0);
    issue(1);
    issue(2);

    for (int ch = 0; ch < 4; ch++) {
        if (ch <= 1)      asm volatile("cp.async.wait_group 2;" ::: "memory");
        else if (ch == 2) asm volatile("cp.async.wait_group 1;" ::: "memory");
        else              asm volatile("cp.async.wait_group 0;" ::: "memory");
        __syncthreads();
        if (ch + 3 < 4) issue(ch + 3);

        const uint32_t sA = smem_base + (ch & 3) * DBUF;
        const uint32_t sB = sA + 64 * DSTRIDE;
#pragma unroll
        for (int ks = 0; ks < 4; ks++) {
            uint32_t a[4];
            {
                const int row = wm * 16 + (lane & 15);
                const uint32_t col = ks * 32 + ((lane >> 4) << 4);
                ldsm_x4(a[0], a[1], a[2], a[3], sA + row * DSTRIDE + col);
            }
            uint32_t b[4][2];
#pragma unroll
            for (int nf = 0; nf < 4; nf++) {
                const int row = wn * 32 + nf * 8 + (lane & 7);
                const uint32_t col = ks * 32 + (((lane >> 3) & 1) << 4);
                ldsm_x2(b[nf][0], b[nf][1], sB + row * DSTRIDE + col);
            }
#pragma unroll
            for (int nf = 0; nf < 4; nf++)
                mma16816(acc[nf], a[0], a[1], a[2], a[3], b[nf][0], b[nf][1]);
        }
    }

    const int r0 = lane >> 2;
    const int c0 = (lane & 3) << 1;
    const int m = bt * 64 + wm * 16 + r0;
    float* dbase = g_dotp[hh] + (((size_t)c * 1024 + m) << 6);
#pragma unroll
    for (int nf = 0; nf < 4; nf++) {
        const int n = wn * 32 + nf * 8 + c0;
        *(float2*)(dbase + n) = make_float2(acc[nf][0], acc[nf][1]);
        *(float2*)(dbase + (8 << 6) + n) = make_float2(acc[nf][2], acc[nf][3]);
    }
}

// ---------------------------------------------------------------------------
// Epilogue: coalesced smem staging of dots, then distances/k_assign.
// One block = 8 b-rows. <<<128, 256>>>
// ---------------------------------------------------------------------------
__global__ void __launch_bounds__(256)
score_epilogue_kernel(float* __restrict__ out_ka, float* __restrict__ out_dist) {
    __shared__ float s_dot[8][8][64];   // [c][bsub][k]  16 KB
    __shared__ float s_cnorm[64];       // [bsub*8+c]
    const int tid = threadIdx.x;
    const int b0 = blockIdx.x;          // b rows b0*8 .. b0*8+7

    // Bulk-load dots: 64 rows (c,bsub) x 64 floats, both halves summed.
    // 1024 float4 positions, 4 per thread, fully coalesced per row.
#pragma unroll
    for (int it = 0; it < 4; it++) {
        const int pos = tid + it * 256;          // 0..1023
        const int r = pos >> 4;                  // 0..63 = c*8+bsub
        const int seg = pos & 15;                // float4 index within row
        const int c = r >> 3, bsub = r & 7;
        const size_t gi = ((((size_t)c * 1024 + b0 * 8 + bsub) << 6) + seg * 4);
        const float4 u = *(const float4*)(g_dotp[0] + gi);
        const float4 v = *(const float4*)(g_dotp[1] + gi);
        *(float4*)&s_dot[c][bsub][seg * 4] =
            make_float4(u.x + v.x, u.y + v.y, u.z + v.z, u.w + v.w);
    }
    if (tid < 64) {
        const int bsub = tid >> 3, cc = tid & 7;
        const int b = b0 * 8 + bsub;
        s_cnorm[tid] = g_cnormp[0][cc * 1024 + b] + g_cnormp[1][cc * 1024 + b]
                     + g_cnormp[2][cc * 1024 + b] + g_cnormp[3][cc * 1024 + b];
    }
    __syncthreads();

    for (int p = tid; p < 400; p += 256) {
        const int bsub = p / 50;
        const int k = p % 50;
        const int b = b0 * 8 + bsub;
        float sc[8];
        float S = 0.f;
#pragma unroll
        for (int c = 0; c < 8; c++) {
            const float d2 = 1.f + s_cnorm[bsub * 8 + c] - 2.f * s_dot[c][bsub][k]
                           + g_munorm[k * 8 + c];
            const float v = 1.f / d2;
            sc[c] = v;
            S += v;
        }
        const float inv1 = 1.f / (S + 1e-8f);
        float dist[8];
        float T = 0.f;
#pragma unroll
        for (int c = 0; c < 8; c++) { dist[c] = sc[c] * inv1; T += dist[c]; }
        const float inv2 = 1.f / T;
        const size_t base = ((size_t)b * 50 + k) << 3;
        float4 d01 = make_float4(dist[0], dist[1], dist[2], dist[3]);
        float4 d23 = make_float4(dist[4], dist[5], dist[6], dist[7]);
        *(float4*)(out_dist + base) = d01;
        *(float4*)(out_dist + base + 4) = d23;
        *(float4*)(out_ka + base) =
            make_float4(d01.x * inv2, d01.y * inv2, d01.z * inv2, d01.w * inv2);
        *(float4*)(out_ka + base + 4) =
            make_float4(d23.x * inv2, d23.y * inv2, d23.z * inv2, d23.w * inv2);
    }
}

// ---------------------------------------------------------------------------
extern "C" void kernel_launch(void* const* d_in, const int* in_sizes, int n_in,
                              void* d_out, int out_size) {
    const float* x        = (const float*)d_in[0];
    const float* class_mu = (const float*)d_in[1];
    const float* mask     = (const float*)d_in[2];
    const float* W        = (const float*)d_in[3];

    float* out      = (float*)d_out;
    float* out_mul  = out;                                  // 1024*8*512
    float* out_ka   = out + (size_t)1024 * 8 * 512;         // 1024*50*8
    float* out_dist = out_ka + (size_t)1024 * 50 * 8;       // 1024*50*8

    const size_t gemm_smem = 4 * BUF_BYTES;  // 81920 B
    const size_t dot_smem  = 4 * DBUF;       // 73728 B
    cudaFuncSetAttribute(mma_gemm_kernel,
                         cudaFuncAttributeMaxDynamicSharedMemorySize, (int)gemm_smem);
    cudaFuncSetAttribute(dot_mma_kernel,
                         cudaFuncAttributeMaxDynamicSharedMemorySize, (int)dot_smem);

    prep_kernel<<<4402, 256>>>(x, mask, W, class_mu);
    mma_gemm_kernel<<<dim3(4, 64), 256, gemm_smem>>>(out_mul);
    dot_mma_kernel<<<256, 256, dot_smem>>>();
    score_epilogue_kernel<<<128, 256>>>(out_ka, out_dist);
}

// round 14
// speedup vs baseline: 1.0166x; 1.0046x over previous
#include <cuda_runtime.h>
#include <cuda_bf16.h>
#include <cstdint>
#include <cstddef>

// B=1024, K=50 classes, C=8 centers, H=512
// inputs: d_in[0]=x[1024,512], d_in[1]=class_mu[50,8,512], d_in[2]=mask[8,512], d_in[3]=W[512,512]
// output: concat(mul[1024,8,512] fp32, k_assign[1024,50,8], distances[1024,50,8])
//
// mask is binary {0,1} => per-center K-compaction of the GEMM is EXACT.

// ---------------------------------------------------------------------------
// Scratch (__device__ globals — allocation-free)
// ---------------------------------------------------------------------------
__device__ int   g_kcnt[8];        // kept count per center
__device__ float g_munorm[400];
// compacted, split A: [c][b][1024]: cols [0,512)=hi(x gathered), [512,1024)=lo
__device__ __align__(16) __nv_bfloat16 g_Axc[8 * 1024 * 1024];
// compacted, split, transposed W: [c][n][1024]: hi | lo
__device__ __align__(16) __nv_bfloat16 g_Wc[8 * 512 * 1024];
// bf16 copy of mul, c-major: [c][b][h]
__device__ __align__(16) __nv_bfloat16 g_mulbf16[8 * 1024 * 512];
// bf16 padded class_mu, c-major: [c][k64][h], zeros for k>=50
__device__ __align__(16) __nv_bfloat16 g_mubf16[8 * 64 * 512];
// dot partials: [half][c][b][k64] fp32
__device__ __align__(16) float g_dotp[2][8 * 1024 * 64];
// per-bn partial ||mul[b,c]||^2: [bn][c*1024+b]
__device__ float g_cnormp[4][8 * 1024];

// ---------------------------------------------------------------------------
// PTX helpers (baseline sm_103 target — no 'a'-suffix features)
// ---------------------------------------------------------------------------
__device__ __forceinline__ uint32_t smem_u32(const void* p) {
    uint32_t a;
    asm("{ .reg .u64 t; cvta.to.shared.u64 t, %1; cvt.u32.u64 %0, t; }"
        : "=r"(a) : "l"(p));
    return a;
}

__device__ __forceinline__ void ldsm_x4(uint32_t& r0, uint32_t& r1, uint32_t& r2,
                                        uint32_t& r3, uint32_t addr) {
    asm volatile("ldmatrix.sync.aligned.m8n8.x4.shared.b16 {%0,%1,%2,%3}, [%4];"
                 : "=r"(r0), "=r"(r1), "=r"(r2), "=r"(r3) : "r"(addr));
}

__device__ __forceinline__ void ldsm_x2(uint32_t& r0, uint32_t& r1, uint32_t addr) {
    asm volatile("ldmatrix.sync.aligned.m8n8.x2.shared.b16 {%0,%1}, [%2];"
                 : "=r"(r0), "=r"(r1) : "r"(addr));
}

__device__ __forceinline__ void mma16816(float* c, uint32_t a0, uint32_t a1,
                                         uint32_t a2, uint32_t a3,
                                         uint32_t b0, uint32_t b1) {
    asm volatile(
        "mma.sync.aligned.m16n8k16.row.col.f32.bf16.bf16.f32 "
        "{%0,%1,%2,%3}, {%4,%5,%6,%7}, {%8,%9}, {%0,%1,%2,%3};"
        : "+f"(c[0]), "+f"(c[1]), "+f"(c[2]), "+f"(c[3])
        : "r"(a0), "r"(a1), "r"(a2), "r"(a3), "r"(b0), "r"(b1));
}

#define CP_ASYNC16(dst, src) \
    asm volatile("cp.async.cg.shared.global [%0], [%1], 16;" \
                 :: "r"(dst), "l"(src) : "memory")
#define CP_COMMIT() asm volatile("cp.async.commit_group;" ::: "memory")

// ---------------------------------------------------------------------------
// In-block mask compaction: 256 threads, warp w owns elements [w*64, w*64+64).
// ---------------------------------------------------------------------------
__device__ __forceinline__ int compact_mask(const float* __restrict__ mask_row,
                                            int tid, int* s_kidx, int* s_wcnt) {
    const int lane = tid & 31;
    const int warp = tid >> 5;  // 0..7
    const int e0 = warp * 64 + lane;
    const int e1 = e0 + 32;
    const int p0 = (mask_row[e0] != 0.f) ? 1 : 0;
    const int p1 = (mask_row[e1] != 0.f) ? 1 : 0;
    const unsigned b0 = __ballot_sync(0xffffffffu, p0);
    const unsigned b1 = __ballot_sync(0xffffffffu, p1);
    const int c0 = __popc(b0);
    if (lane == 0) s_wcnt[warp] = c0 + __popc(b1);
    __syncthreads();
    int base = 0, total = 0;
#pragma unroll
    for (int w = 0; w < 8; w++) {
        if (w < warp) base += s_wcnt[w];
        total += s_wcnt[w];
    }
    if (p0) s_kidx[base + __popc(b0 & ((1u << lane) - 1u))] = e0;
    if (p1) s_kidx[base + c0 + __popc(b1 & ((1u << lane) - 1u))] = e1;
    for (int j = total + tid; j < 512; j += 256) s_kidx[j] = 0;
    __syncthreads();
    return total;
}

// ---------------------------------------------------------------------------
// Prep: gather+split A (4 rows/blk) | gather+transpose+split W | munorm | mubf16
// grid = 2048 + 2048 + 50 + 256 = 4402, 256 threads
// ---------------------------------------------------------------------------
__global__ void prep_kernel(const float* __restrict__ x,
                            const float* __restrict__ mask,
                            const float* __restrict__ W,
                            const float* __restrict__ class_mu) {
    __shared__ int s_kidx[512];
    __shared__ int s_wcnt[8];
    __shared__ float s_x[4][512];
    __shared__ float tile[32][33];
    const int tid = threadIdx.x;
    const int blk = blockIdx.x;

    if (blk < 2048) {
        // ---- gather + split A: 4 b-rows per block ----
        const int c = blk >> 8;
        const int bq = blk & 255;
        for (int i = tid; i < 4 * 512; i += 256)
            s_x[i >> 9][i & 511] = x[(size_t)(bq * 4 + (i >> 9)) * 512 + (i & 511)];
        const int total = compact_mask(mask + c * 512, tid, s_kidx, s_wcnt);
        if (bq == 0 && tid == 0) g_kcnt[c] = total;
        const int nch32 = ((total + 31) >> 5) << 5;
        const int j2 = tid * 2;
        if (j2 < nch32) {
            const int i0 = s_kidx[j2];
            const int i1 = s_kidx[j2 + 1];
            const bool v0ok = j2 < total, v1ok = (j2 + 1) < total;
#pragma unroll
            for (int r = 0; r < 4; r++) {
                const float v0 = v0ok ? s_x[r][i0] : 0.f;
                const float v1 = v1ok ? s_x[r][i1] : 0.f;
                const __nv_bfloat16 h0 = __float2bfloat16(v0);
                const __nv_bfloat16 h1 = __float2bfloat16(v1);
                const __nv_bfloat16 l0 = __float2bfloat16(v0 - __bfloat162float(h0));
                const __nv_bfloat16 l1 = __float2bfloat16(v1 - __bfloat162float(h1));
                __nv_bfloat16* base =
                    g_Axc + (((size_t)c * 1024 + bq * 4 + r) << 10);
                *(__nv_bfloat162*)(base + j2)       = __halves2bfloat162(h0, h1);
                *(__nv_bfloat162*)(base + 512 + j2) = __halves2bfloat162(l0, l1);
            }
        }
    } else if (blk < 4096) {
        // ---- gather + transpose + split W ----
        const int t = blk - 2048;
        const int c = t >> 8;
        const int jt = (t >> 4) & 15, nt = t & 15;
        const int total = compact_mask(mask + c * 512, tid, s_kidx, s_wcnt);
        const int nch32 = ((total + 31) >> 5) << 5;
        if (jt * 32 >= nch32) return;
        const int tx = tid & 31, ty = tid >> 5;
#pragma unroll
        for (int i = 0; i < 32; i += 8) {
            const int j = jt * 32 + ty + i;
            tile[ty + i][tx] = (j < total)
                ? W[(size_t)s_kidx[j] * 512 + nt * 32 + tx] : 0.f;
        }
        __syncthreads();
#pragma unroll
        for (int i = 0; i < 32; i += 8) {
            const int n = nt * 32 + ty + i;
            const int j = jt * 32 + tx;
            const float v = tile[tx][ty + i];
            const __nv_bfloat16 hi = __float2bfloat16(v);
            const __nv_bfloat16 lo = __float2bfloat16(v - __bfloat162float(hi));
            __nv_bfloat16* base = g_Wc + (((size_t)c * 512 + n) << 10);
            base[j] = hi;
            base[512 + j] = lo;
        }
    } else if (blk < 4096 + 50) {
        // ---- munorm ----
        const int warp = tid >> 5;
        const int lane = tid & 31;
        const int r = (blk - 4096) * 8 + warp;
        const float4* row = (const float4*)(class_mu + (size_t)r * 512);
        float s = 0.f;
#pragma unroll
        for (int j = lane; j < 128; j += 32) {
            float4 v = row[j];
            s += v.x * v.x + v.y * v.y + v.z * v.z + v.w * v.w;
        }
#pragma unroll
        for (int o = 16; o; o >>= 1) s += __shfl_down_sync(0xffffffffu, s, o);
        if (lane == 0) g_munorm[r] = s;
    } else {
        // ---- class_mu -> g_mubf16[c][k64][h], zero padded ----
        const int t = blk - 4146;
        const int idx4 = t * 256 + tid;
        const int row = idx4 >> 7;
        const int h = (idx4 & 127) << 2;
        const int c = row >> 6, k = row & 63;
        float4 v = make_float4(0.f, 0.f, 0.f, 0.f);
        if (k < 50) v = *(const float4*)(class_mu + (((size_t)k * 8 + c) << 9) + h);
        __nv_bfloat162* dst = (__nv_bfloat162*)(g_mubf16 + (size_t)row * 512 + h);
        dst[0] = __halves2bfloat162(__float2bfloat16(v.x), __float2bfloat16(v.y));
        dst[1] = __halves2bfloat162(__float2bfloat16(v.z), __float2bfloat16(v.w));
    }
}

// ---------------------------------------------------------------------------
// K-compacted HMMA GEMM, per-center: mul[b,c,:] = Axc[c] @ Wc[c]^T
// <<<dim3(4, 64), 256, 81920>>>, blockIdx.y = c*8 + bm
// ---------------------------------------------------------------------------
#define SM_STRIDE 80
#define BUF_BYTES 20480

__global__ void __launch_bounds__(256, 2)
mma_gemm_kernel(float* __restrict__ out) {
    extern __shared__ __align__(16) char smem[];  // 4 * BUF_BYTES
    __shared__ float s_part[4][128];
    const uint32_t smem_base = smem_u32(smem);

    const int tid = threadIdx.x;
    const int lane = tid & 31;
    const int wid = tid >> 5;
    const int wm = wid >> 2;
    const int wn = wid & 3;
    const int bn = blockIdx.x;
    const int c  = blockIdx.y >> 3;
    const int bm = blockIdx.y & 7;

    const int kcnt = g_kcnt[c];
    const int nch = (kcnt + 31) >> 5;
    const int T = 3 * nch;

    const __nv_bfloat16* Abase = g_Axc + (((size_t)c * 1024 + bm * 128) << 10);
    const __nv_bfloat16* Bbase = g_Wc  + (((size_t)c * 512  + bn * 128) << 10);

    const int lrow = tid >> 2;
    const int lseg = tid & 3;

    auto issue = [&](int t) {
        const int stage = t & 3;
        const int p = (t >= 2 * nch) ? 2 : ((t >= nch) ? 1 : 0);
        const int sub = t - p * nch;
        const int acol = ((p == 2) ? 512 : 0) + sub * 32;  // A: hi,hi,lo
        const int bcol = ((p == 1) ? 512 : 0) + sub * 32;  // B: hi,lo,hi
        const uint32_t sA = smem_base + stage * BUF_BYTES;
        const uint32_t sB = sA + 128 * SM_STRIDE;
#pragma unroll
        for (int q = 0; q < 2; q++) {
            const int row = lrow + q * 64;
            CP_ASYNC16(sA + row * SM_STRIDE + lseg * 16,
                       Abase + ((size_t)row << 10) + acol + lseg * 8);
        }
#pragma unroll
        for (int q = 0; q < 2; q++) {
            const int row = lrow + q * 64;
            CP_ASYNC16(sB + row * SM_STRIDE + lseg * 16,
                       Bbase + ((size_t)row << 10) + bcol + lseg * 8);
        }
        CP_COMMIT();
    };

    float acc[4][4][4];
#pragma unroll
    for (int i = 0; i < 4; i++)
#pragma unroll
        for (int j = 0; j < 4; j++)
#pragma unroll
            for (int q = 0; q < 4; q++) acc[i][j][q] = 0.f;

    issue(0);
    issue(1);
    issue(2);

    for (int t = 0; t < T; t++) {
        if (t <= T - 3)      asm volatile("cp.async.wait_group 2;" ::: "memory");
        else if (t == T - 2) asm volatile("cp.async.wait_group 1;" ::: "memory");
        else                 asm volatile("cp.async.wait_group 0;" ::: "memory");
        __syncthreads();
        if (t + 3 < T) issue(t + 3);

        const uint32_t sA = smem_base + (t & 3) * BUF_BYTES;
        const uint32_t sB = sA + 128 * SM_STRIDE;
#pragma unroll
        for (int ks = 0; ks < 2; ks++) {
            uint32_t a[4][4];
#pragma unroll
            for (int mf = 0; mf < 4; mf++) {
                const int row = wm * 64 + mf * 16 + (lane & 15);
                const uint32_t col = ks * 32 + ((lane >> 4) << 4);
                ldsm_x4(a[mf][0], a[mf][1], a[mf][2], a[mf][3],
                        sA + row * SM_STRIDE + col);
            }
            uint32_t b[4][2];
#pragma unroll
            for (int nf = 0; nf < 4; nf++) {
                const int row = wn * 32 + nf * 8 + (lane & 7);
                const uint32_t col = ks * 32 + (((lane >> 3) & 1) << 4);
                ldsm_x2(b[nf][0], b[nf][1], sB + row * SM_STRIDE + col);
            }
#pragma unroll
            for (int mf = 0; mf < 4; mf++)
#pragma unroll
                for (int nf = 0; nf < 4; nf++)
                    mma16816(acc[mf][nf], a[mf][0], a[mf][1], a[mf][2], a[mf][3],
                             b[nf][0], b[nf][1]);
        }
    }

    // ---- Epilogue 1: stores (fp32 out, bf16 c-major copy) ----
    const int r0 = lane >> 2;
    const int c0 = (lane & 3) << 1;
#pragma unroll
    for (int mf = 0; mf < 4; mf++) {
        const int bl = bm * 128 + wm * 64 + mf * 16 + r0;
#pragma unroll
        for (int nf = 0; nf < 4; nf++) {
            const int n = bn * 128 + wn * 32 + nf * 8 + c0;
            *(float2*)(out + (((size_t)bl * 8 + c) << 9) + n) =
                make_float2(acc[mf][nf][0], acc[mf][nf][1]);
            *(float2*)(out + (((size_t)(bl + 8) * 8 + c) << 9) + n) =
                make_float2(acc[mf][nf][2], acc[mf][nf][3]);
            *(__nv_bfloat162*)(g_mulbf16 + (((size_t)c * 1024 + bl) << 9) + n) =
                __halves2bfloat162(__float2bfloat16(acc[mf][nf][0]),
                                   __float2bfloat16(acc[mf][nf][1]));
            *(__nv_bfloat162*)(g_mulbf16 + (((size_t)c * 1024 + bl + 8) << 9) + n) =
                __halves2bfloat162(__float2bfloat16(acc[mf][nf][2]),
                                   __float2bfloat16(acc[mf][nf][3]));
        }
    }

    // ---- Epilogue 2: partial cnorm over this CTA's 128 n-cols ----
#pragma unroll
    for (int mf = 0; mf < 4; mf++) {
        float p1 = 0.f, p2 = 0.f;
#pragma unroll
        for (int nf = 0; nf < 4; nf++) {
            p1 += acc[mf][nf][0] * acc[mf][nf][0] + acc[mf][nf][1] * acc[mf][nf][1];
            p2 += acc[mf][nf][2] * acc[mf][nf][2] + acc[mf][nf][3] * acc[mf][nf][3];
        }
        p1 += __shfl_xor_sync(0xffffffffu, p1, 1);
        p1 += __shfl_xor_sync(0xffffffffu, p1, 2);
        p2 += __shfl_xor_sync(0xffffffffu, p2, 1);
        p2 += __shfl_xor_sync(0xffffffffu, p2, 2);
        if ((lane & 3) == 0) {
            s_part[wn][wm * 64 + mf * 16 + r0] = p1;
            s_part[wn][wm * 64 + mf * 16 + r0 + 8] = p2;
        }
    }
    __syncthreads();
    if (tid < 128) {
        const float cn = s_part[0][tid] + s_part[1][tid]
                       + s_part[2][tid] + s_part[3][tid];
        g_cnormp[bn][c * 1024 + bm * 128 + tid] = cn;
    }
}

// ---------------------------------------------------------------------------
// Dot HMMA (h-split by 2): g_dotp[hh][c][b][k64] partial over 256 h-cols.
// <<<256, 256, 73728>>>, blockIdx.x = hh*128 + bt*8 + c
// ---------------------------------------------------------------------------
#define DSTRIDE 144
#define DBUF (128 * DSTRIDE)

__global__ void __launch_bounds__(256)
dot_mma_kernel() {
    extern __shared__ __align__(16) char smem[];  // 4 * DBUF
    const uint32_t smem_base = smem_u32(smem);

    const int tid = threadIdx.x;
    const int lane = tid & 31;
    const int wid = tid >> 5;
    const int wm = wid >> 1;
    const int wn = wid & 1;
    const int c = blockIdx.x & 7;
    const int bt = (blockIdx.x >> 3) & 15;
    const int hh = blockIdx.x >> 7;

    const __nv_bfloat16* Abase =
        g_mulbf16 + (((size_t)c * 1024 + bt * 64) << 9) + hh * 256;
    const __nv_bfloat16* Bbase = g_mubf16 + ((size_t)c << 15) + hh * 256;

    const int lrow = tid >> 3;
    const int lseg = tid & 7;

    auto issue = [&](int ch) {
        const int stage = ch & 3;
        const uint32_t sA = smem_base + stage * DBUF;
        const uint32_t sB = sA + 64 * DSTRIDE;
#pragma unroll
        for (int q = 0; q < 2; q++) {
            const int row = lrow + q * 32;
            CP_ASYNC16(sA + row * DSTRIDE + lseg * 16,
                       Abase + ((size_t)row << 9) + ch * 64 + lseg * 8);
        }
#pragma unroll
        for (int q = 0; q < 2; q++) {
            const int row = lrow + q * 32;
            CP_ASYNC16(sB + row * DSTRIDE + lseg * 16,
                       Bbase + ((size_t)row << 9) + ch * 64 + lseg * 8);
        }
        CP_COMMIT();
    };

    float acc[4][4];
#pragma unroll
    for (int j = 0; j < 4; j++)
#pragma unroll
        for (int q = 0; q < 4; q++) acc[j][q] = 0.f;

    issue(0);
    issue(1);
    issue(2);

    for (int ch = 0; ch < 4; ch++) {
        if (ch <= 1)      asm volatile("cp.async.wait_group 2;" ::: "memory");
        else if (ch == 2) asm volatile("cp.async.wait_group 1;" ::: "memory");
        else              asm volatile("cp.async.wait_group 0;" ::: "memory");
        __syncthreads();
        if (ch + 3 < 4) issue(ch + 3);

        const uint32_t sA = smem_base + (ch & 3) * DBUF;
        const uint32_t sB = sA + 64 * DSTRIDE;
#pragma unroll
        for (int ks = 0; ks < 4; ks++) {
            uint32_t a[4];
            {
                const int row = wm * 16 + (lane & 15);
                const uint32_t col = ks * 32 + ((lane >> 4) << 4);
                ldsm_x4(a[0], a[1], a[2], a[3], sA + row * DSTRIDE + col);
            }
            uint32_t b[4][2];
#pragma unroll
            for (int nf = 0; nf < 4; nf++) {
                const int row = wn * 32 + nf * 8 + (lane & 7);
                const uint32_t col = ks * 32 + (((lane >> 3) & 1) << 4);
                ldsm_x2(b[nf][0], b[nf][1], sB + row * DSTRIDE + col);
            }
#pragma unroll
            for (int nf = 0; nf < 4; nf++)
                mma16816(acc[nf], a[0], a[1], a[2], a[3], b[nf][0], b[nf][1]);
        }
    }

    const int r0 = lane >> 2;
    const int c0 = (lane & 3) << 1;
    const int m = bt * 64 + wm * 16 + r0;
    float* dbase = g_dotp[hh] + (((size_t)c * 1024 + m) << 6);
#pragma unroll
    for (int nf = 0; nf < 4; nf++) {
        const int n = wn * 32 + nf * 8 + c0;
        *(float2*)(dbase + n) = make_float2(acc[nf][0], acc[nf][1]);
        *(float2*)(dbase + (8 << 6) + n) = make_float2(acc[nf][2], acc[nf][3]);
    }
}

// ---------------------------------------------------------------------------
// Epilogue: coalesced smem staging of dots, then distances/k_assign.
// One block = 8 b-rows. <<<128, 256>>>
// ---------------------------------------------------------------------------
__global__ void __launch_bounds__(256)
score_epilogue_kernel(float* __restrict__ out_ka, float* __restrict__ out_dist) {
    __shared__ float s_dot[8][8][64];   // [c][bsub][k]  16 KB
    __shared__ float s_cnorm[64];       // [bsub*8+c]
    const int tid = threadIdx.x;
    const int b0 = blockIdx.x;          // b rows b0*8 .. b0*8+7

    // Bulk-load dots: 64 rows (c,bsub) x 64 floats, both halves summed.
    // 1024 float4 positions, 4 per thread, fully coalesced per row.
#pragma unroll
    for (int it = 0; it < 4; it++) {
        const int pos = tid + it * 256;          // 0..1023
        const int r = pos >> 4;                  // 0..63 = c*8+bsub
        const int seg = pos & 15;                // float4 index within row
        const int c = r >> 3, bsub = r & 7;
        const size_t gi = ((((size_t)c * 1024 + b0 * 8 + bsub) << 6) + seg * 4);
        const float4 u = *(const float4*)(g_dotp[0] + gi);
        const float4 v = *(const float4*)(g_dotp[1] + gi);
        *(float4*)&s_dot[c][bsub][seg * 4] =
            make_float4(u.x + v.x, u.y + v.y, u.z + v.z, u.w + v.w);
    }
    if (tid < 64) {
        const int bsub = tid >> 3, cc = tid & 7;
        const int b = b0 * 8 + bsub;
        s_cnorm[tid] = g_cnormp[0][cc * 1024 + b] + g_cnormp[1][cc * 1024 + b]
                     + g_cnormp[2][cc * 1024 + b] + g_cnormp[3][cc * 1024 + b];
    }
    __syncthreads();

    for (int p = tid; p < 400; p += 256) {
        const int bsub = p / 50;
        const int k = p % 50;
        const int b = b0 * 8 + bsub;
        float sc[8];
        float S = 0.f;
#pragma unroll
        for (int c = 0; c < 8; c++) {
            const float d2 = 1.f + s_cnorm[bsub * 8 + c] - 2.f * s_dot[c][bsub][k]
                           + g_munorm[k * 8 + c];
            const float v = 1.f / d2;
            sc[c] = v;
            S += v;
        }
        const float inv1 = 1.f / (S + 1e-8f);
        float dist[8];
        float T = 0.f;
#pragma unroll
        for (int c = 0; c < 8; c++) { dist[c] = sc[c] * inv1; T += dist[c]; }
        const float inv2 = 1.f / T;
        const size_t base = ((size_t)b * 50 + k) << 3;
        float4 d01 = make_float4(dist[0], dist[1], dist[2], dist[3]);
        float4 d23 = make_float4(dist[4], dist[5], dist[6], dist[7]);
        *(float4*)(out_dist + base) = d01;
        *(float4*)(out_dist + base + 4) = d23;
        *(float4*)(out_ka + base) =
            make_float4(d01.x * inv2, d01.y * inv2, d01.z * inv2, d01.w * inv2);
        *(float4*)(out_ka + base + 4) =
            make_float4(d23.x * inv2, d23.y * inv2, d23.z * inv2, d23.w * inv2);
    }
}

// ---------------------------------------------------------------------------
extern "C" void kernel_launch(void* const* d_in, const int* in_sizes, int n_in,
                              void* d_out, int out_size) {
    const float* x        = (const float*)d_in[0];
    const float* class_mu = (const float*)d_in[1];
    const float* mask     = (const float*)d_in[2];
    const float* W        = (const float*)d_in[3];

    float* out      = (float*)d_out;
    float* out_mul  = out;                                  // 1024*8*512
    float* out_ka   = out + (size_t)1024 * 8 * 512;         // 1024*50*8
    float* out_dist = out_ka + (size_t)1024 * 50 * 8;       // 1024*50*8

    const size_t gemm_smem = 4 * BUF_BYTES;  // 81920 B
    const size_t dot_smem  = 4 * DBUF;       // 73728 B
    cudaFuncSetAttribute(mma_gemm_kernel,
                         cudaFuncAttributeMaxDynamicSharedMemorySize, (int)gemm_smem);
    cudaFuncSetAttribute(dot_mma_kernel,
                         cudaFuncAttributeMaxDynamicSharedMemorySize, (int)dot_smem);

    prep_kernel<<<4402, 256>>>(x, mask, W, class_mu);
    mma_gemm_kernel<<<dim3(4, 64), 256, gemm_smem>>>(out_mul);
    dot_mma_kernel<<<256, 256, dot_smem>>>();
    score_epilogue_kernel<<<128, 256>>>(out_ka, out_dist);
}